// round 11
// baseline (speedup 1.0000x reference)
#include <cuda_runtime.h>
#include <math.h>
#include <stdint.h>

// ---------------------------------------------------------------------------
// Round 11 (resubmit of R10 after infra failure; static audit clean):
// batch-split twin blocks. Each block: 8 batches x 256 neurons (2/thread).
// Twin blocks (adjacent blockIdx, batch halves 0/1) stream the SAME weights
// -> DRAM once, twin hits L2. Depth-2 weight prefetch, depth-4 act LDS
// pipeline, cp.async double-buffer, grids 1216/1200.
// ---------------------------------------------------------------------------

#define BB 16
#define BBH 8                 // batches per block
#define TT 50
#define XX 3600
#define E4N 4800
#define I4N 1200
#define E23N 4800
#define I23N 1200
#define IN4E 13200
#define IN4I 16800
#define IN23E 6000
#define IN23I 9600

#define GBDIM 128
#define NPB 256               // neurons per block (2 per thread)

#define S4E  32               // NCH=75  -> grid 19*32*2 = 1216
#define S4I  120              // NCH=225 -> grid 5*120*2 = 1200
#define S23E 32               // NCH=45  -> grid 1216
#define S23I 120              // NCH=135 -> grid 1200

// WT layout offsets (float4 units)
#define OFF4E  0ull
#define OFF4I  21600000ull
#define OFF23E 27000000ull
#define OFF23I 39960000ull

__device__ float4 g_WT[43200000];     // 691.2 MB transposed weights
__device__ float  g_partial[2600000]; // split-K partials

__device__ __forceinline__ void fma2(unsigned long long& d,
                                     unsigned long long a,
                                     unsigned long long b) {
    asm("fma.rn.f32x2 %0, %1, %2, %0;" : "+l"(d) : "l"(a), "l"(b));
}

// ---- fused transpose: all 8 matrices in one launch ------------------------
struct TransP {
    const float* src[8];
    float4* dst[8];
    int K[8], N[8], tk[8], cnt[8];
};

__global__ __launch_bounds__(256) void transpose_all_kernel(TransP p) {
    __shared__ float tile[64][17];
    int tl = blockIdx.x;
    int mi = 0;
#pragma unroll
    for (int m = 0; m < 7; ++m) {
        if (mi == m && tl >= p.cnt[m]) { tl -= p.cnt[m]; mi = m + 1; }
    }
    const float* W = p.src[mi];
    float4* out = p.dst[mi];
    const int K = p.K[mi], N = p.N[mi], tk = p.tk[mi];
    const int k0 = (tl % tk) * 16;
    const int n0 = (tl / tk) * 64;
    const int t = threadIdx.x;
    const int row = t >> 2;
    const int kk = (t & 3) * 4;
    if (n0 + row < N) {
        const float4 v = *reinterpret_cast<const float4*>(
            W + (size_t)(n0 + row) * K + k0 + kk);
        tile[row][kk] = v.x; tile[row][kk + 1] = v.y;
        tile[row][kk + 2] = v.z; tile[row][kk + 3] = v.w;
    }
    __syncthreads();
    const int k4l = t >> 6;
    const int n = t & 63;
    if (n0 + n < N)
        out[(size_t)(k0 / 4 + k4l) * N + n0 + n] =
            make_float4(tile[n][4 * k4l], tile[n][4 * k4l + 1],
                        tile[n][4 * k4l + 2], tile[n][4 * k4l + 3]);
}

// ---- gemvt ---------------------------------------------------------------
struct CellP {
    const float4* wt;
    const float* act[5];
    int ld[5];
    int nch[5];
    int seg4off[5];
    int nseg;
    int N, nb, S, NCH;
};

template <int NP_>
__global__ __launch_bounds__(GBDIM, 4) void gemvt_kernel(CellP a) {
    __shared__ float4 s_act[2][BBH][NP_];
    const int t = threadIdx.x;
    // twin decode: adjacent bids = same (g,s), batch halves 0/1
    const int bh = blockIdx.x & 1;
    const int rest = blockIdx.x >> 1;
    const int g = rest % a.nb;
    const int s = rest / a.nb;
    const int boff = bh * BBH;
    const int n0 = g * NPB + t;
    const int n1 = n0 + GBDIM;
    const bool gok0 = n0 < a.N;
    const bool gok1 = n1 < a.N;
    const int m0 = gok0 ? n0 : 0;
    const int m1 = gok1 ? n1 : 0;
    const int NN = a.N;

    const int cpb = a.NCH / a.S;
    const int rem = a.NCH % a.S;
    const int start = s * cpb + (s < rem ? s : rem);
    const int cnt = cpb + (s < rem ? 1 : 0);

    auto desc = [&](int gc, const float*& ap, int& ld, int& k0, int& w4) {
        int c = gc, sg = 0;
#pragma unroll
        for (int i = 0; i < 4; ++i) {
            if (sg < a.nseg - 1 && c >= a.nch[sg]) { c -= a.nch[sg]; ++sg; }
        }
        ap = a.act[sg];
        ld = a.ld[sg];
        k0 = c * (NP_ * 4);
        w4 = a.seg4off[sg] + c * NP_;
    };

    auto stage = [&](int gc, int buf) {
        const float* ap; int ld, k0, w4;
        desc(gc, ap, ld, k0, w4);
        for (int x = t; x < NP_ * BBH; x += GBDIM) {
            const int b = x / NP_;
            const int j = x - b * NP_;
            const float* src = ap + (size_t)(boff + b) * ld + k0 + 4 * j;
            uint32_t dst =
                (uint32_t)__cvta_generic_to_shared(&s_act[buf][b][j]);
            asm volatile("cp.async.cg.shared.global [%0], [%1], 16;"
                         :: "r"(dst), "l"(src));
        }
        asm volatile("cp.async.commit_group;");
    };

    unsigned long long acc0[BBH], acc1[BBH];
#pragma unroll
    for (int b = 0; b < BBH; ++b) { acc0[b] = 0ull; acc1[b] = 0ull; }

    auto compute = [&](int gc, int buf) {
        const float* ap; int ld, k0, w4;
        desc(gc, ap, ld, k0, w4);
        const float4* __restrict__ wp0 = a.wt + (size_t)w4 * NN + m0;
        const float4* __restrict__ wp1 = a.wt + (size_t)w4 * NN + m1;
        float4 wa0 = __ldcs(wp0);
        float4 wb0 = __ldcs(wp1);
        float4 wa1 = __ldcs(wp0 + NN);
        float4 wb1 = __ldcs(wp1 + NN);
        wp0 += 2 * NN; wp1 += 2 * NN;
        const ulonglong2* __restrict__ sa =
            reinterpret_cast<const ulonglong2*>(&s_act[buf][0][0]);
#pragma unroll 2
        for (int q = 0; q < NP_; ++q) {
            const float4 wa = wa0;
            const float4 wb = wb0;
            wa0 = wa1; wb0 = wb1;
            if (q < NP_ - 2) {
                wa1 = __ldcs(wp0);
                wb1 = __ldcs(wp1);
                wp0 += NN; wp1 += NN;
            }
            const ulonglong2 wva = *reinterpret_cast<const ulonglong2*>(&wa);
            const ulonglong2 wvb = *reinterpret_cast<const ulonglong2*>(&wb);
            ulonglong2 avp[4];
            avp[0] = sa[0 * NP_ + q];
            avp[1] = sa[1 * NP_ + q];
            avp[2] = sa[2 * NP_ + q];
#pragma unroll
            for (int b = 0; b < BBH; ++b) {
                if (b + 3 < BBH) avp[(b + 3) & 3] = sa[(b + 3) * NP_ + q];
                const ulonglong2 av = avp[b & 3];
                fma2(acc0[b], wva.x, av.x);
                fma2(acc1[b], wvb.x, av.x);
                fma2(acc0[b], wva.y, av.y);
                fma2(acc1[b], wvb.y, av.y);
            }
        }
    };

    stage(start, 0);
    for (int i = 0; i < cnt; ++i) {
        if (i + 1 < cnt) {
            stage(start + i + 1, (i + 1) & 1);
            asm volatile("cp.async.wait_group 1;");
        } else {
            asm volatile("cp.async.wait_group 0;");
        }
        __syncthreads();
        compute(start + i, i & 1);
        __syncthreads();
    }

#pragma unroll
    for (int b = 0; b < BBH; ++b) {
        const float2 f0 = *reinterpret_cast<const float2*>(&acc0[b]);
        const float2 f1 = *reinterpret_cast<const float2*>(&acc1[b]);
        float* dst = g_partial + ((size_t)s * BB + (boff + b)) * NN;
        if (gok0) dst[n0] = f0.x + f0.y;
        if (gok1) dst[n1] = f1.x + f1.y;
    }
}

// ---- reduce: sum splits + bias + tanh (float4) ---------------------------
__global__ __launch_bounds__(256) void reduce_kernel(
    const float4* __restrict__ bih, const float4* __restrict__ bhh,
    float* __restrict__ out, int N4, int S, int out_ld) {
    const int idx = blockIdx.x * 256 + threadIdx.x;
    if (idx >= BB * N4) return;
    const int n4 = idx % N4;
    const int b = idx / N4;
    const float4 bi = bih[n4];
    const float4 bh = bhh[n4];
    float4 sum = make_float4(bi.x + bh.x, bi.y + bh.y,
                             bi.z + bh.z, bi.w + bh.w);
    const float4* part = (const float4*)g_partial;
    for (int s = 0; s < S; ++s) {
        const float4 p = part[((size_t)s * BB + b) * N4 + n4];
        sum.x += p.x; sum.y += p.y; sum.z += p.z; sum.w += p.w;
    }
    const float4 r = make_float4(tanhf(sum.x), tanhf(sum.y),
                                 tanhf(sum.z), tanhf(sum.w));
    *reinterpret_cast<float4*>(out + (size_t)b * out_ld + 4 * n4) = r;
}

// ---------------------------------------------------------------------------
extern "C" void kernel_launch(void* const* d_in, const int* in_sizes, int n_in,
                              void* d_out, int out_size) {
    const float* x_on   = (const float*)d_in[0];
    const float* x_off  = (const float*)d_in[1];
    const float* h4e0   = (const float*)d_in[2];
    const float* h4i0   = (const float*)d_in[3];
    const float* h23e0  = (const float*)d_in[4];
    const float* h23i0  = (const float*)d_in[5];
    const float* Wih4e  = (const float*)d_in[6];
    const float* Whh4e  = (const float*)d_in[7];
    const float* bih4e  = (const float*)d_in[8];
    const float* bhh4e  = (const float*)d_in[9];
    const float* Wih4i  = (const float*)d_in[10];
    const float* Whh4i  = (const float*)d_in[11];
    const float* bih4i  = (const float*)d_in[12];
    const float* bhh4i  = (const float*)d_in[13];
    const float* Wih23e = (const float*)d_in[14];
    const float* Whh23e = (const float*)d_in[15];
    const float* bih23e = (const float*)d_in[16];
    const float* bhh23e = (const float*)d_in[17];
    const float* Wih23i = (const float*)d_in[18];
    const float* Whh23i = (const float*)d_in[19];
    const float* bih23i = (const float*)d_in[20];
    const float* bhh23i = (const float*)d_in[21];

    float4* wtp = 0;
    cudaGetSymbolAddress((void**)&wtp, g_WT);

    // ---- one fused transpose launch ----
    {
        TransP p;
        const float* srcs[8] = {Wih4e, Whh4e, Wih4i, Whh4i,
                                Wih23e, Whh23e, Wih23i, Whh23i};
        float4* dsts[8] = {
            wtp + OFF4E,  wtp + OFF4E  + (size_t)(IN4E / 4) * E4N,
            wtp + OFF4I,  wtp + OFF4I  + (size_t)(IN4I / 4) * I4N,
            wtp + OFF23E, wtp + OFF23E + (size_t)(IN23E / 4) * E23N,
            wtp + OFF23I, wtp + OFF23I + (size_t)(IN23I / 4) * I23N};
        const int Ks[8] = {IN4E, E4N, IN4I, I4N, IN23E, E23N, IN23I, I23N};
        const int Ns[8] = {E4N, E4N, I4N, I4N, E23N, E23N, I23N, I23N};
        int total = 0;
        for (int i = 0; i < 8; ++i) {
            p.src[i] = srcs[i]; p.dst[i] = dsts[i];
            p.K[i] = Ks[i]; p.N[i] = Ns[i];
            p.tk[i] = Ks[i] / 16;
            p.cnt[i] = p.tk[i] * ((Ns[i] + 63) / 64);
            total += p.cnt[i];
        }
        transpose_all_kernel<<<total, 256>>>(p);
    }

    float* out = (float*)d_out;
    float* y4e  = out;
    float* y4i  = y4e  + (size_t)BB * TT * E4N;
    float* y23e = y4i  + (size_t)BB * TT * I4N;
    float* y23i = y23e + (size_t)BB * TT * E23N;

    CellP c4e, c4i, c23e, c23i;
    // E cells: CHUNK=240 (NP=60)
    c4e.wt = wtp + OFF4E; c4e.N = E4N; c4e.nb = 19; c4e.S = S4E;
    c4e.NCH = 75; c4e.nseg = 5;
    {   const int C[5] = {15, 15, 5, 20, 20};
        const int O[5] = {0, 900, 1800, 2100, 3300};
        for (int i = 0; i < 5; ++i) { c4e.nch[i]=C[i]; c4e.seg4off[i]=O[i]; } }

    c23e.wt = wtp + OFF23E; c23e.N = E23N; c23e.nb = 19; c23e.S = S23E;
    c23e.NCH = 45; c23e.nseg = 3;
    {   const int C[5] = {20, 5, 20, 0, 0};
        const int O[5] = {0, 1200, 1500, 0, 0};
        for (int i = 0; i < 5; ++i) { c23e.nch[i]=C[i]; c23e.seg4off[i]=O[i]; } }

    // I cells: CHUNK=80 (NP=20)
    c4i.wt = wtp + OFF4I; c4i.N = I4N; c4i.nb = 5; c4i.S = S4I;
    c4i.NCH = 225; c4i.nseg = 5;
    {   const int C[5] = {45, 45, 60, 60, 15};
        const int O[5] = {0, 900, 1800, 3000, 4200};
        for (int i = 0; i < 5; ++i) { c4i.nch[i]=C[i]; c4i.seg4off[i]=O[i]; } }

    c23i.wt = wtp + OFF23I; c23i.N = I23N; c23i.nb = 5; c23i.S = S23I;
    c23i.NCH = 135; c23i.nseg = 3;
    {   const int C[5] = {60, 60, 15, 0, 0};
        const int O[5] = {0, 1200, 2400, 0, 0};
        for (int i = 0; i < 5; ++i) { c23i.nch[i]=C[i]; c23i.seg4off[i]=O[i]; } }

    for (int t = 0; t < TT; ++t) {
        const float* p4e  = t ? (y4e  + (size_t)(t - 1) * E4N)  : h4e0;
        const int    l4e  = t ? TT * E4N  : E4N;
        const float* p4i  = t ? (y4i  + (size_t)(t - 1) * I4N)  : h4i0;
        const int    l4i  = t ? TT * I4N  : I4N;
        const float* p23e = t ? (y23e + (size_t)(t - 1) * E23N) : h23e0;
        const int    l23e = t ? TT * E23N : E23N;
        const float* p23i = t ? (y23i + (size_t)(t - 1) * I23N) : h23i0;
        const int    l23i = t ? TT * I23N : I23N;

        const float* xon_t  = x_on  + (size_t)t * XX;
        const float* xoff_t = x_off + (size_t)t * XX;

        float* o4e  = y4e  + (size_t)t * E4N;
        float* o4i  = y4i  + (size_t)t * I4N;
        float* o23e = y23e + (size_t)t * E23N;
        float* o23i = y23i + (size_t)t * I23N;

        c4e.act[0] = xon_t;  c4e.ld[0] = TT * XX;
        c4e.act[1] = xoff_t; c4e.ld[1] = TT * XX;
        c4e.act[2] = p4i;    c4e.ld[2] = l4i;
        c4e.act[3] = p23e;   c4e.ld[3] = l23e;
        c4e.act[4] = p4e;    c4e.ld[4] = l4e;
        gemvt_kernel<60><<<19 * S4E * 2, GBDIM>>>(c4e);
        reduce_kernel<<<(BB * E4N / 4 + 255) / 256, 256>>>(
            (const float4*)bih4e, (const float4*)bhh4e, o4e,
            E4N / 4, S4E, TT * E4N);

        c4i.act[0] = xon_t;  c4i.ld[0] = TT * XX;
        c4i.act[1] = xoff_t; c4i.ld[1] = TT * XX;
        c4i.act[2] = o4e;    c4i.ld[2] = TT * E4N;
        c4i.act[3] = p23e;   c4i.ld[3] = l23e;
        c4i.act[4] = p4i;    c4i.ld[4] = l4i;
        gemvt_kernel<20><<<5 * S4I * 2, GBDIM>>>(c4i);
        reduce_kernel<<<(BB * I4N / 4 + 255) / 256, 256>>>(
            (const float4*)bih4i, (const float4*)bhh4i, o4i,
            I4N / 4, S4I, TT * I4N);

        c23e.act[0] = o4e;  c23e.ld[0] = TT * E4N;
        c23e.act[1] = p23i; c23e.ld[1] = l23i;
        c23e.act[2] = p23e; c23e.ld[2] = l23e;
        gemvt_kernel<60><<<19 * S23E * 2, GBDIM>>>(c23e);
        reduce_kernel<<<(BB * E23N / 4 + 255) / 256, 256>>>(
            (const float4*)bih23e, (const float4*)bhh23e, o23e,
            E23N / 4, S23E, TT * E23N);

        c23i.act[0] = o4e;  c23i.ld[0] = TT * E4N;
        c23i.act[1] = o23e; c23i.ld[1] = TT * E23N;
        c23i.act[2] = p23i; c23i.ld[2] = l23i;
        gemvt_kernel<20><<<5 * S23I * 2, GBDIM>>>(c23i);
        reduce_kernel<<<(BB * I23N / 4 + 255) / 256, 256>>>(
            (const float4*)bih23i, (const float4*)bhh23i, o23i,
            I23N / 4, S23I, TT * I23N);
    }
    (void)in_sizes; (void)n_in; (void)out_size;
}

// round 16
// speedup vs baseline: 1.5455x; 1.5455x over previous
#include <cuda_runtime.h>
#include <math.h>
#include <stdint.h>

// ---------------------------------------------------------------------------
// Round 16: R15 + TAIL DRAIN FIX. cp.async wait_group(2) only covers
// compute(j) while new groups keep being committed; the last two iterations
// committed no groups, so compute read undrained weight subtiles
// (rel_err 2.4e-2). Fix: peel tail waits to wait_group(1)/wait_group(0).
// Design: cp.async weight pipeline (4-stage ring, 8KB subtiles), 2
// neurons/thread, 16 batches, 4-deep act LDS pipeline, split-K, float4
// reduce kernels. E cells CHUNK=120 (NP=30), I cells CHUNK=80 (NP=20).
// ---------------------------------------------------------------------------

#define BB 16
#define TT 50
#define XX 3600
#define E4N 4800
#define I4N 1200
#define E23N 4800
#define I23N 1200
#define IN4E 13200
#define IN4I 16800
#define IN23E 6000
#define IN23I 9600

#define GBDIM 128
#define NPB 256               // neurons per block (2 per thread)
#define KSUB 2                // k4-rows per weight subtile
#define STG 4                 // cp.async pipeline stages

#define S4E  32               // NCH=150 -> grid 608
#define S4I  120              // NCH=225 -> grid 600
#define S23E 32               // NCH=90  -> grid 608
#define S23I 120              // NCH=135 -> grid 600

// WT layout offsets (float4 units)
#define OFF4E  0ull
#define OFF4I  21600000ull
#define OFF23E 27000000ull
#define OFF23I 39960000ull

__device__ float4 g_WT[43202048];     // +2048 pad for staging col overhang
__device__ float  g_partial[2600000]; // split-K partials

__device__ __forceinline__ void fma2(unsigned long long& d,
                                     unsigned long long a,
                                     unsigned long long b) {
    asm("fma.rn.f32x2 %0, %1, %2, %0;" : "+l"(d) : "l"(a), "l"(b));
}

// ---- fused transpose: all 8 matrices in one launch ------------------------
struct TransP {
    const float* src[8];
    float4* dst[8];
    int K[8], N[8], tk[8], cnt[8];
};

__global__ __launch_bounds__(256) void transpose_all_kernel(TransP p) {
    __shared__ float tile[64][17];
    int tl = blockIdx.x;
    int mi = 0;
#pragma unroll
    for (int m = 0; m < 7; ++m) {
        if (mi == m && tl >= p.cnt[m]) { tl -= p.cnt[m]; mi = m + 1; }
    }
    const float* W = p.src[mi];
    float4* out = p.dst[mi];
    const int K = p.K[mi], N = p.N[mi], tk = p.tk[mi];
    const int k0 = (tl % tk) * 16;
    const int n0 = (tl / tk) * 64;
    const int t = threadIdx.x;
    const int row = t >> 2;
    const int kk = (t & 3) * 4;
    if (n0 + row < N) {
        const float4 v = *reinterpret_cast<const float4*>(
            W + (size_t)(n0 + row) * K + k0 + kk);
        tile[row][kk] = v.x; tile[row][kk + 1] = v.y;
        tile[row][kk + 2] = v.z; tile[row][kk + 3] = v.w;
    }
    __syncthreads();
    const int k4l = t >> 6;
    const int n = t & 63;
    if (n0 + n < N)
        out[(size_t)(k0 / 4 + k4l) * N + n0 + n] =
            make_float4(tile[n][4 * k4l], tile[n][4 * k4l + 1],
                        tile[n][4 * k4l + 2], tile[n][4 * k4l + 3]);
}

// ---- gemvt ---------------------------------------------------------------
struct CellP {
    const float4* wt;
    const float* act[5];
    int ld[5];
    int nch[5];          // chunks per segment
    int seg4off[5];      // float4-row offset of segment start
    int nseg;
    int N, nb, S, NCH;
};

template <int NP_>
__global__ __launch_bounds__(GBDIM, 4) void gemvt_kernel(CellP a) {
    constexpr int NSUB = NP_ / KSUB;
    __shared__ float4 s_act[2][BB][NP_];
    __shared__ float4 s_w[STG][KSUB][NPB];
    const int t = threadIdx.x;
    const int g = blockIdx.x % a.nb;
    const int s = blockIdx.x / a.nb;
    const int n0 = g * NPB + t;
    const int n1 = n0 + GBDIM;
    const bool gok0 = n0 < a.N;
    const bool gok1 = n1 < a.N;
    const int NN = a.N;
    const int ncol = g * NPB;

    const int cpb = a.NCH / a.S;
    const int rem = a.NCH % a.S;
    const int start = s * cpb + (s < rem ? s : rem);
    const int cnt = cpb + (s < rem ? 1 : 0);
    const int total = cnt * NSUB;

    auto desc = [&](int gc, const float*& ap, int& ld, int& k0, int& w4) {
        int c = gc, sg = 0;
#pragma unroll
        for (int i = 0; i < 4; ++i) {
            if (sg < a.nseg - 1 && c >= a.nch[sg]) { c -= a.nch[sg]; ++sg; }
        }
        ap = a.act[sg];
        ld = a.ld[sg];
        k0 = c * (NP_ * 4);
        w4 = a.seg4off[sg] + c * NP_;
    };

    // issue subtile j (1 commit group per subtile; act rides with sub==0)
    auto issue = [&](int j) {
        const int cl = j / NSUB;
        const int sub = j - cl * NSUB;
        const float* ap; int ld, k0, w4;
        desc(start + cl, ap, ld, k0, w4);
        if (sub == 0) {
            const int buf = cl & 1;
            for (int x = t; x < NP_ * BB; x += GBDIM) {
                const int b = x / NP_;
                const int jj = x - b * NP_;
                const float* src = ap + (size_t)b * ld + k0 + 4 * jj;
                uint32_t dst =
                    (uint32_t)__cvta_generic_to_shared(&s_act[buf][b][jj]);
                asm volatile("cp.async.cg.shared.global [%0], [%1], 16;"
                             :: "r"(dst), "l"(src));
            }
        }
        const int slot = j & (STG - 1);
        const float4* wsrc = a.wt + (size_t)(w4 + sub * KSUB) * NN + ncol;
#pragma unroll
        for (int x = t; x < KSUB * NPB; x += GBDIM) {
            const int r = x / NPB;
            const int col = x - r * NPB;
            const float4* src = wsrc + (size_t)r * NN + col;
            uint32_t dst =
                (uint32_t)__cvta_generic_to_shared(&s_w[slot][r][col]);
            asm volatile("cp.async.cg.shared.global [%0], [%1], 16;"
                         :: "r"(dst), "l"(src));
        }
        asm volatile("cp.async.commit_group;");
    };

    unsigned long long acc0[BB], acc1[BB];
#pragma unroll
    for (int b = 0; b < BB; ++b) { acc0[b] = 0ull; acc1[b] = 0ull; }

    auto compute = [&](int j) {
        const int cl = j / NSUB;
        const int sub = j - cl * NSUB;
        const int buf = cl & 1;
        const int slot = j & (STG - 1);
        const int q0 = sub * KSUB;
        const ulonglong2* __restrict__ sa =
            reinterpret_cast<const ulonglong2*>(&s_act[buf][0][0]);
#pragma unroll
        for (int r = 0; r < KSUB; ++r) {
            const int q = q0 + r;
            const float4 wa = s_w[slot][r][t];
            const float4 wb = s_w[slot][r][t + GBDIM];
            const ulonglong2 wva = *reinterpret_cast<const ulonglong2*>(&wa);
            const ulonglong2 wvb = *reinterpret_cast<const ulonglong2*>(&wb);
            ulonglong2 avp[4];
            avp[0] = sa[0 * NP_ + q];
            avp[1] = sa[1 * NP_ + q];
            avp[2] = sa[2 * NP_ + q];
#pragma unroll
            for (int b = 0; b < BB; ++b) {
                if (b + 3 < BB) avp[(b + 3) & 3] = sa[(b + 3) * NP_ + q];
                const ulonglong2 av = avp[b & 3];
                fma2(acc0[b], wva.x, av.x);
                fma2(acc1[b], wvb.x, av.x);
                fma2(acc0[b], wva.y, av.y);
                fma2(acc1[b], wvb.y, av.y);
            }
        }
    };

    // ---- software pipeline with PEELED TAIL WAITS:
    // steady state: groups 0..j+2 committed -> wait_group(2) covers group j.
    // tail (no new commits): must tighten to wait_group(1), then wait_group(0)
    // so compute(j) never reads an undrained weight subtile.
    const int nprol = (total < STG - 1) ? total : STG - 1;
    for (int j = 0; j < nprol; ++j) issue(j);
    for (int j = 0; j < total; ++j) {
        if (j + 2 < total) {
            asm volatile("cp.async.wait_group 2;");
        } else if (j + 1 < total) {
            asm volatile("cp.async.wait_group 1;");
        } else {
            asm volatile("cp.async.wait_group 0;");
        }
        __syncthreads();
        if (j + STG - 1 < total) issue(j + STG - 1);
        compute(j);
    }

#pragma unroll
    for (int b = 0; b < BB; ++b) {
        const float2 f0 = *reinterpret_cast<const float2*>(&acc0[b]);
        const float2 f1 = *reinterpret_cast<const float2*>(&acc1[b]);
        float* dst = g_partial + ((size_t)s * BB + b) * NN;
        if (gok0) dst[n0] = f0.x + f0.y;
        if (gok1) dst[n1] = f1.x + f1.y;
    }
}

// ---- reduce: sum splits + bias + tanh (float4) ---------------------------
__global__ __launch_bounds__(256) void reduce_kernel(
    const float4* __restrict__ bih, const float4* __restrict__ bhh,
    float* __restrict__ out, int N4, int S, int out_ld) {
    const int idx = blockIdx.x * 256 + threadIdx.x;
    if (idx >= BB * N4) return;
    const int n4 = idx % N4;
    const int b = idx / N4;
    const float4 bi = bih[n4];
    const float4 bh = bhh[n4];
    float4 sum = make_float4(bi.x + bh.x, bi.y + bh.y,
                             bi.z + bh.z, bi.w + bh.w);
    const float4* part = (const float4*)g_partial;
    for (int s = 0; s < S; ++s) {
        const float4 p = part[((size_t)s * BB + b) * N4 + n4];
        sum.x += p.x; sum.y += p.y; sum.z += p.z; sum.w += p.w;
    }
    const float4 r = make_float4(tanhf(sum.x), tanhf(sum.y),
                                 tanhf(sum.z), tanhf(sum.w));
    *reinterpret_cast<float4*>(out + (size_t)b * out_ld + 4 * n4) = r;
}

// ---------------------------------------------------------------------------
extern "C" void kernel_launch(void* const* d_in, const int* in_sizes, int n_in,
                              void* d_out, int out_size) {
    const float* x_on   = (const float*)d_in[0];
    const float* x_off  = (const float*)d_in[1];
    const float* h4e0   = (const float*)d_in[2];
    const float* h4i0   = (const float*)d_in[3];
    const float* h23e0  = (const float*)d_in[4];
    const float* h23i0  = (const float*)d_in[5];
    const float* Wih4e  = (const float*)d_in[6];
    const float* Whh4e  = (const float*)d_in[7];
    const float* bih4e  = (const float*)d_in[8];
    const float* bhh4e  = (const float*)d_in[9];
    const float* Wih4i  = (const float*)d_in[10];
    const float* Whh4i  = (const float*)d_in[11];
    const float* bih4i  = (const float*)d_in[12];
    const float* bhh4i  = (const float*)d_in[13];
    const float* Wih23e = (const float*)d_in[14];
    const float* Whh23e = (const float*)d_in[15];
    const float* bih23e = (const float*)d_in[16];
    const float* bhh23e = (const float*)d_in[17];
    const float* Wih23i = (const float*)d_in[18];
    const float* Whh23i = (const float*)d_in[19];
    const float* bih23i = (const float*)d_in[20];
    const float* bhh23i = (const float*)d_in[21];

    float4* wtp = 0;
    cudaGetSymbolAddress((void**)&wtp, g_WT);

    // ---- one fused transpose launch ----
    {
        TransP p;
        const float* srcs[8] = {Wih4e, Whh4e, Wih4i, Whh4i,
                                Wih23e, Whh23e, Wih23i, Whh23i};
        float4* dsts[8] = {
            wtp + OFF4E,  wtp + OFF4E  + (size_t)(IN4E / 4) * E4N,
            wtp + OFF4I,  wtp + OFF4I  + (size_t)(IN4I / 4) * I4N,
            wtp + OFF23E, wtp + OFF23E + (size_t)(IN23E / 4) * E23N,
            wtp + OFF23I, wtp + OFF23I + (size_t)(IN23I / 4) * I23N};
        const int Ks[8] = {IN4E, E4N, IN4I, I4N, IN23E, E23N, IN23I, I23N};
        const int Ns[8] = {E4N, E4N, I4N, I4N, E23N, E23N, I23N, I23N};
        int total = 0;
        for (int i = 0; i < 8; ++i) {
            p.src[i] = srcs[i]; p.dst[i] = dsts[i];
            p.K[i] = Ks[i]; p.N[i] = Ns[i];
            p.tk[i] = Ks[i] / 16;
            p.cnt[i] = p.tk[i] * ((Ns[i] + 63) / 64);
            total += p.cnt[i];
        }
        transpose_all_kernel<<<total, 256>>>(p);
    }

    float* out = (float*)d_out;
    float* y4e  = out;
    float* y4i  = y4e  + (size_t)BB * TT * E4N;
    float* y23e = y4i  + (size_t)BB * TT * I4N;
    float* y23i = y23e + (size_t)BB * TT * E23N;

    CellP c4e, c4i, c23e, c23i;
    // E cells: CHUNK=120 (NP=30)
    c4e.wt = wtp + OFF4E; c4e.N = E4N; c4e.nb = 19; c4e.S = S4E;
    c4e.NCH = 150; c4e.nseg = 5;
    {   const int C[5] = {30, 30, 10, 40, 40};
        const int O[5] = {0, 900, 1800, 2100, 3300};
        for (int i = 0; i < 5; ++i) { c4e.nch[i]=C[i]; c4e.seg4off[i]=O[i]; } }

    c23e.wt = wtp + OFF23E; c23e.N = E23N; c23e.nb = 19; c23e.S = S23E;
    c23e.NCH = 90; c23e.nseg = 3;
    {   const int C[5] = {40, 10, 40, 0, 0};
        const int O[5] = {0, 1200, 1500, 0, 0};
        for (int i = 0; i < 5; ++i) { c23e.nch[i]=C[i]; c23e.seg4off[i]=O[i]; } }

    // I cells: CHUNK=80 (NP=20)
    c4i.wt = wtp + OFF4I; c4i.N = I4N; c4i.nb = 5; c4i.S = S4I;
    c4i.NCH = 225; c4i.nseg = 5;
    {   const int C[5] = {45, 45, 60, 60, 15};
        const int O[5] = {0, 900, 1800, 3000, 4200};
        for (int i = 0; i < 5; ++i) { c4i.nch[i]=C[i]; c4i.seg4off[i]=O[i]; } }

    c23i.wt = wtp + OFF23I; c23i.N = I23N; c23i.nb = 5; c23i.S = S23I;
    c23i.NCH = 135; c23i.nseg = 3;
    {   const int C[5] = {60, 60, 15, 0, 0};
        const int O[5] = {0, 1200, 2400, 0, 0};
        for (int i = 0; i < 5; ++i) { c23i.nch[i]=C[i]; c23i.seg4off[i]=O[i]; } }

    for (int t = 0; t < TT; ++t) {
        const float* p4e  = t ? (y4e  + (size_t)(t - 1) * E4N)  : h4e0;
        const int    l4e  = t ? TT * E4N  : E4N;
        const float* p4i  = t ? (y4i  + (size_t)(t - 1) * I4N)  : h4i0;
        const int    l4i  = t ? TT * I4N  : I4N;
        const float* p23e = t ? (y23e + (size_t)(t - 1) * E23N) : h23e0;
        const int    l23e = t ? TT * E23N : E23N;
        const float* p23i = t ? (y23i + (size_t)(t - 1) * I23N) : h23i0;
        const int    l23i = t ? TT * I23N : I23N;

        const float* xon_t  = x_on  + (size_t)t * XX;
        const float* xoff_t = x_off + (size_t)t * XX;

        float* o4e  = y4e  + (size_t)t * E4N;
        float* o4i  = y4i  + (size_t)t * I4N;
        float* o23e = y23e + (size_t)t * E23N;
        float* o23i = y23i + (size_t)t * I23N;

        c4e.act[0] = xon_t;  c4e.ld[0] = TT * XX;
        c4e.act[1] = xoff_t; c4e.ld[1] = TT * XX;
        c4e.act[2] = p4i;    c4e.ld[2] = l4i;
        c4e.act[3] = p23e;   c4e.ld[3] = l23e;
        c4e.act[4] = p4e;    c4e.ld[4] = l4e;
        gemvt_kernel<30><<<19 * S4E, GBDIM>>>(c4e);
        reduce_kernel<<<(BB * E4N / 4 + 255) / 256, 256>>>(
            (const float4*)bih4e, (const float4*)bhh4e, o4e,
            E4N / 4, S4E, TT * E4N);

        c4i.act[0] = xon_t;  c4i.ld[0] = TT * XX;
        c4i.act[1] = xoff_t; c4i.ld[1] = TT * XX;
        c4i.act[2] = o4e;    c4i.ld[2] = TT * E4N;
        c4i.act[3] = p23e;   c4i.ld[3] = l23e;
        c4i.act[4] = p4i;    c4i.ld[4] = l4i;
        gemvt_kernel<20><<<5 * S4I, GBDIM>>>(c4i);
        reduce_kernel<<<(BB * I4N / 4 + 255) / 256, 256>>>(
            (const float4*)bih4i, (const float4*)bhh4i, o4i,
            I4N / 4, S4I, TT * I4N);

        c23e.act[0] = o4e;  c23e.ld[0] = TT * E4N;
        c23e.act[1] = p23i; c23e.ld[1] = l23i;
        c23e.act[2] = p23e; c23e.ld[2] = l23e;
        gemvt_kernel<30><<<19 * S23E, GBDIM>>>(c23e);
        reduce_kernel<<<(BB * E23N / 4 + 255) / 256, 256>>>(
            (const float4*)bih23e, (const float4*)bhh23e, o23e,
            E23N / 4, S23E, TT * E23N);

        c23i.act[0] = o4e;  c23i.ld[0] = TT * E4N;
        c23i.act[1] = o23e; c23i.ld[1] = TT * E23N;
        c23i.act[2] = p23i; c23i.ld[2] = l23i;
        gemvt_kernel<20><<<5 * S23I, GBDIM>>>(c23i);
        reduce_kernel<<<(BB * I23N / 4 + 255) / 256, 256>>>(
            (const float4*)bih23i, (const float4*)bhh23i, o23i,
            I23N / 4, S23I, TT * I23N);
    }
    (void)in_sizes; (void)n_in; (void)out_size;
}